// round 14
// baseline (speedup 1.0000x reference)
#include <cuda_runtime.h>
#include <cuda_fp16.h>
#include <cstdint>

// ---------------------------------------------------------------------------
// Dims / tiling
// ---------------------------------------------------------------------------
static constexpr int DK = 4096;   // inner
static constexpr int DM = 8192;   // rows of x
static constexpr int DN = 16384;  // output channels

static constexpr int BM = 128, BN = 256, BK = 64;
static constexpr int STAGES  = 4;
static constexpr int KITERS  = DK / BK;                 // 64
static constexpr int A_BYTES = BM * BK * 2;             // 16 KB  (128 rows x 128B)
static constexpr int B_BYTES = BN * BK * 2;             // 32 KB  (256 rows x 128B)
static constexpr int STAGE_BYTES = A_BYTES + B_BYTES;   // 48 KB
static constexpr int SMEM_TOTAL  = STAGES * STAGE_BYTES;// 192 KB

// fp16 scratch (static device globals — the allowed scratch path)
__device__ __align__(1024) __half g_wdeq[(size_t)DN * DK];  // 128 MB
__device__ __align__(1024) __half g_xh[(size_t)DM * DK];    //  64 MB

// ---------------------------------------------------------------------------
// Base-ISA helpers (legal on compute_103 WITHOUT the 'a' suffix)
// ---------------------------------------------------------------------------
__device__ __forceinline__ uint32_t s2u(const void* p) {
    uint32_t a;
    asm("{ .reg .u64 t; cvta.to.shared.u64 t, %1; cvt.u32.u64 %0, t; }"
        : "=r"(a) : "l"(p));
    return a;
}

__device__ __forceinline__ void cp16(uint32_t dst, const void* src) {
    asm volatile("cp.async.cg.shared.global [%0], [%1], 16;"
                 :: "r"(dst), "l"(src) : "memory");
}

__device__ __forceinline__ void cp_commit() {
    asm volatile("cp.async.commit_group;" ::: "memory");
}

template <int N>
__device__ __forceinline__ void cp_wait() {
    asm volatile("cp.async.wait_group %0;" :: "n"(N) : "memory");
}

__device__ __forceinline__ void ldsm4(uint32_t* r, uint32_t addr) {
    asm volatile("ldmatrix.sync.aligned.m8n8.x4.shared.b16 {%0,%1,%2,%3}, [%4];"
                 : "=r"(r[0]), "=r"(r[1]), "=r"(r[2]), "=r"(r[3]) : "r"(addr));
}

__device__ __forceinline__ void mma16816(float* d, const uint32_t* a,
                                         uint32_t b0, uint32_t b1) {
    asm volatile(
        "mma.sync.aligned.m16n8k16.row.col.f32.f16.f16.f32 "
        "{%0,%1,%2,%3}, {%4,%5,%6,%7}, {%8,%9}, {%0,%1,%2,%3};"
        : "+f"(d[0]), "+f"(d[1]), "+f"(d[2]), "+f"(d[3])
        : "r"(a[0]), "r"(a[1]), "r"(a[2]), "r"(a[3]), "r"(b0), "r"(b1));
}

// Swizzled smem byte offset: 128B rows, 16B chunk c XORed with (row & 7).
// Conflict-free for both the cp.async stores and the ldmatrix reads.
__device__ __forceinline__ uint32_t swz(int row, int chunk) {
    return (uint32_t)(row * 128 + ((chunk ^ (row & 7)) << 4));
}

// ---------------------------------------------------------------------------
// Pre-pass 1: x fp32-carrier -> fp16 (values are exactly fp16-representable).
// 8 elems/thread: two float4 loads, one uint4 (8-half) store. Fully coalesced.
// ---------------------------------------------------------------------------
__global__ void __launch_bounds__(256) convert_x_kernel(const float* __restrict__ x) {
    size_t i = (size_t)blockIdx.x * 256 + threadIdx.x;  // elements [8i, 8i+8)
    float4 v0 = __ldg((const float4*)x + 2 * i);
    float4 v1 = __ldg((const float4*)x + 2 * i + 1);
    __half2 r[4];
    r[0] = __floats2half2_rn(v0.x, v0.y);
    r[1] = __floats2half2_rn(v0.z, v0.w);
    r[2] = __floats2half2_rn(v1.x, v1.y);
    r[3] = __floats2half2_rn(v1.z, v1.w);
    *((uint4*)g_xh + i) = *(uint4*)r;
}

// ---------------------------------------------------------------------------
// Pre-pass 2: W fp16[n,k] = (half(w_int32) + off[n]) * scale[n] — exact fp16
// add/mul, matching the reference's fp16 dequant arithmetic.
// ---------------------------------------------------------------------------
__global__ void __launch_bounds__(256) dequant_kernel(const int* __restrict__ w,
                                                      const float* __restrict__ sc,
                                                      const float* __restrict__ off) {
    size_t i = (size_t)blockIdx.x * 256 + threadIdx.x;  // elements [8i, 8i+8)
    int row = (int)(i >> 9);                            // (8i) / 4096
    int4 v0 = __ldg((const int4*)w + 2 * i);
    int4 v1 = __ldg((const int4*)w + 2 * i + 1);
    __half2 s2 = __half2half2(__float2half(sc[row]));
    __half2 o2 = __half2half2(__float2half(off[row]));
    __half2 r[4];
    r[0] = __hmul2(__hadd2(__floats2half2_rn((float)v0.x, (float)v0.y), o2), s2);
    r[1] = __hmul2(__hadd2(__floats2half2_rn((float)v0.z, (float)v0.w), o2), s2);
    r[2] = __hmul2(__hadd2(__floats2half2_rn((float)v1.x, (float)v1.y), o2), s2);
    r[3] = __hmul2(__hadd2(__floats2half2_rn((float)v1.z, (float)v1.w), o2), s2);
    *((uint4*)g_wdeq + i) = *(uint4*)r;
}

// ---------------------------------------------------------------------------
// GEMM: 128x256x64 CTA tile, 8 warps (2m x 4n), warp tile 64x64,
// 4-stage cp.async pipeline, ldmatrix + mma.sync m16n8k16 (fp32 accum).
// Output: fp32 accum -> fp16 round (matches reference cast) -> fp32 store.
// ---------------------------------------------------------------------------
__global__ void __launch_bounds__(256, 1)
gemm_kernel(float* __restrict__ out) {
    extern __shared__ char smem[];
    const uint32_t sbase = s2u(smem);
    const int tid  = threadIdx.x;
    const int wid  = tid >> 5, lane = tid & 31;
    const int wm   = wid & 1;
    const int wnn  = wid >> 1;

    // CTA tile mapping: m-fast (keeps the 64MB A matrix L2-resident),
    // n grouped by 8 tiles so each supergroup's working set fits L2.
    const int cid = blockIdx.x;
    const int g   = cid >> 9;                 // 8 groups of 512 CTAs
    const int r   = cid & 511;
    const int m0  = (r & 63) * BM;
    const int n0  = ((g << 3) + (r >> 6)) * BN;

    // ---- cp.async producer (all 256 threads) ----
    auto issue = [&](int kt) {
        const int stage = kt & (STAGES - 1);
        const uint32_t sA = sbase + stage * STAGE_BYTES;
        const uint32_t sB = sA + A_BYTES;
        const int k0 = kt * BK;
#pragma unroll
        for (int i = 0; i < 4; i++) {
            int idx = tid + i * 256;
            int row = idx >> 3, c = idx & 7;
            cp16(sA + swz(row, c), g_xh + (size_t)(m0 + row) * DK + k0 + c * 8);
        }
#pragma unroll
        for (int i = 0; i < 8; i++) {
            int idx = tid + i * 256;
            int row = idx >> 3, c = idx & 7;
            cp16(sB + swz(row, c), g_wdeq + (size_t)(n0 + row) * DK + k0 + c * 8);
        }
    };

    issue(0); cp_commit();
    issue(1); cp_commit();
    issue(2); cp_commit();

    // ldmatrix lane addressing (PTX fragment maps):
    // A tiles: lanes 0-7 rows0-7/k0-7, 8-15 rows8-15/k0-7,
    //          16-23 rows0-7/k8-15, 24-31 rows8-15/k8-15.
    const int a_row = wm * 64 + (lane & 15);
    const int a_ch  = lane >> 4;
    // B tiles (row=n, 8 halves of k per 16B chunk):
    //          lanes 0-7 n0-7/k0-7, 8-15 n0-7/k8-15,
    //          16-23 n8-15/k0-7, 24-31 n8-15/k8-15.
    const int b_row = wnn * 64 + ((lane >> 4) << 3) + (lane & 7);
    const int b_ch  = (lane >> 3) & 1;

    float acc[4][8][4];
#pragma unroll
    for (int mi = 0; mi < 4; mi++)
#pragma unroll
        for (int n8 = 0; n8 < 8; n8++)
#pragma unroll
            for (int q = 0; q < 4; q++) acc[mi][n8][q] = 0.f;

    for (int kt = 0; kt < KITERS; ++kt) {
        if (kt + 3 < KITERS) issue(kt + 3);
        cp_commit();                       // always commit: keeps group count aligned
        cp_wait<3>();                      // tile kt's group complete
        __syncthreads();

        const uint32_t sA = sbase + (kt & (STAGES - 1)) * STAGE_BYTES;
        const uint32_t sB = sA + A_BYTES;

#pragma unroll
        for (int ks = 0; ks < 4; ++ks) {   // BK=64 -> 4 x k16 steps
            uint32_t a[4][4];
#pragma unroll
            for (int mi = 0; mi < 4; mi++)
                ldsm4(a[mi], sA + swz(a_row + mi * 16, ks * 2 + a_ch));
            uint32_t b[4][4];
#pragma unroll
            for (int nb = 0; nb < 4; nb++)
                ldsm4(b[nb], sB + swz(b_row + nb * 16, ks * 2 + b_ch));
#pragma unroll
            for (int mi = 0; mi < 4; mi++)
#pragma unroll
                for (int n8 = 0; n8 < 8; n8++) {
                    const int nb = n8 >> 1;
                    const int hi = (n8 & 1) << 1;   // even n8 -> b[.][0,1], odd -> b[.][2,3]
                    mma16816(acc[mi][n8], a[mi], b[nb][hi], b[nb][hi + 1]);
                }
        }
        __syncthreads();                    // reads done before this stage is refilled
    }

    // ---- Epilogue: round to fp16 (reference's final cast), store as fp32 ----
    const int orow0 = m0 + wm * 64 + (lane >> 2);
    const int ocol0 = n0 + wnn * 64 + ((lane & 3) << 1);
#pragma unroll
    for (int mi = 0; mi < 4; mi++) {
#pragma unroll
        for (int n8 = 0; n8 < 8; n8++) {
            __half2 h0 = __floats2half2_rn(acc[mi][n8][0], acc[mi][n8][1]);
            __half2 h1 = __floats2half2_rn(acc[mi][n8][2], acc[mi][n8][3]);
            float2 f0 = __half22float2(h0);
            float2 f1 = __half22float2(h1);
            size_t base = (size_t)(orow0 + mi * 16) * DN + ocol0 + n8 * 8;
            *(float2*)(out + base)                   = f0;   // row lane/4
            *(float2*)(out + base + 8 * (size_t)DN)  = f1;   // row lane/4 + 8
        }
    }
}

// ---------------------------------------------------------------------------
// Host launch — inputs arrive as carriers: x fp32, weight int32, scale/offset
// fp32; output buffer is fp32.
// ---------------------------------------------------------------------------
extern "C" void kernel_launch(void* const* d_in, const int* in_sizes, int n_in,
                              void* d_out, int out_size) {
    (void)in_sizes; (void)n_in; (void)out_size;
    const float* x   = (const float*)d_in[0];
    const int*   w   = (const int*)d_in[1];
    const float* sc  = (const float*)d_in[2];
    const float* off = (const float*)d_in[3];
    float*       out = (float*)d_out;

    // 1) x fp32 -> fp16 scratch (exact)
    convert_x_kernel<<<(int)(((size_t)DM * DK) / (256 * 8)), 256>>>(x);

    // 2) Dequant int32 -> fp16 scratch (exact fp16 add/mul, matches reference)
    dequant_kernel<<<(int)(((size_t)DN * DK) / (256 * 8)), 256>>>(w, sc, off);

    // 3) GEMM: 64 x 64 tiles = 4096 CTAs, 256 threads, 192KB dynamic smem
    cudaFuncSetAttribute(gemm_kernel, cudaFuncAttributeMaxDynamicSharedMemorySize,
                         SMEM_TOTAL);
    gemm_kernel<<<(DM / BM) * (DN / BN), 256, SMEM_TOTAL>>>(out);
}